// round 5
// baseline (speedup 1.0000x reference)
#include <cuda_runtime.h>
#include <cuda_bf16.h>
#include <cstdint>

#define HWPIX 3136
#define NELEM 51380224       // 64*256*3136
#define TFAC 0.05f

// ---- scratch (device globals; allocations forbidden) ----
__device__ __nv_bfloat16 g_xhi[NELEM], g_xlo[NELEM];   // x   NHWC hi/lo
__device__ __nv_bfloat16 g_ahi[NELEM], g_alo[NELEM];   // act1 NHWC hi/lo
__device__ float g_buf1[NELEM];                        // conv1 out NHWC fp32
__device__ float g_buf2[NELEM];                        // conv2 out NHWC fp32
__device__ __nv_bfloat16 g_ws[2][9][65536];            // sign weights [pos][co*256+ci]
__device__ unsigned int g_absmax[2];
__device__ double g_wsum[2];
__device__ unsigned long long g_wcnt[2];
__device__ double g_bnsum[2][256], g_bnsq[2][256];
__device__ float g_bnscale[2][256], g_bnshift[2][256];

// ---------------- mma.sync (sm_80+ portable, runs on tensor pipe) ------------
__device__ __forceinline__ void mma16816(float* d, const uint32_t* a,
                                         const uint32_t* b) {
    asm volatile(
        "mma.sync.aligned.m16n8k16.row.col.f32.bf16.bf16.f32 "
        "{%0,%1,%2,%3}, {%4,%5,%6,%7}, {%8,%9}, {%0,%1,%2,%3};"
        : "+f"(d[0]), "+f"(d[1]), "+f"(d[2]), "+f"(d[3])
        : "r"(a[0]), "r"(a[1]), "r"(a[2]), "r"(a[3]), "r"(b[0]), "r"(b[1]));
}

// ---------------- small kernels ----------------------------------------------
__global__ void init_k() {
    int t = threadIdx.x;
    if (t < 2) { g_absmax[t] = 0u; g_wsum[t] = 0.0; g_wcnt[t] = 0ull; }
    g_bnsum[0][t] = 0.0; g_bnsum[1][t] = 0.0;
    g_bnsq[0][t] = 0.0;  g_bnsq[1][t] = 0.0;
}

__global__ void absmax_k(const float* __restrict__ w, int sel) {
    float m = 0.f;
    for (int i = blockIdx.x * blockDim.x + threadIdx.x; i < 589824;
         i += gridDim.x * blockDim.x)
        m = fmaxf(m, fabsf(w[i]));
#pragma unroll
    for (int o = 16; o; o >>= 1) m = fmaxf(m, __shfl_xor_sync(~0u, m, o));
    __shared__ float sm[8];
    if ((threadIdx.x & 31) == 0) sm[threadIdx.x >> 5] = m;
    __syncthreads();
    if (threadIdx.x == 0) {
        float mm = sm[0];
#pragma unroll
        for (int i = 1; i < 8; i++) mm = fmaxf(mm, sm[i]);
        atomicMax(&g_absmax[sel], __float_as_uint(mm));
    }
}

__global__ void wsum_k(const float* __restrict__ w, int sel) {
    float th = TFAC * __uint_as_float(g_absmax[sel]);
    double s = 0.0;
    unsigned int c = 0;
    for (int i = blockIdx.x * blockDim.x + threadIdx.x; i < 589824;
         i += gridDim.x * blockDim.x) {
        float v = w[i];
        if (v >= th || v <= -th) { s += (double)fabsf(v); c++; }
    }
#pragma unroll
    for (int o = 16; o; o >>= 1) {
        s += __shfl_xor_sync(~0u, s, o);
        c += __shfl_xor_sync(~0u, c, o);
    }
    __shared__ double ss[8];
    __shared__ unsigned int sc_[8];
    if ((threadIdx.x & 31) == 0) { ss[threadIdx.x >> 5] = s; sc_[threadIdx.x >> 5] = c; }
    __syncthreads();
    if (threadIdx.x == 0) {
        double S = 0.0; unsigned long long C = 0ull;
#pragma unroll
        for (int i = 0; i < 8; i++) { S += ss[i]; C += sc_[i]; }
        atomicAdd(&g_wsum[sel], S);
        atomicAdd(&g_wcnt[sel], C);
    }
}

__global__ void wsign_k(const float* __restrict__ w, int sel) {
    int i = blockIdx.x * 256 + threadIdx.x;   // co*256+ci
    float th = TFAC * __uint_as_float(g_absmax[sel]);
#pragma unroll
    for (int k = 0; k < 9; k++) {
        float v = w[(size_t)i * 9 + k];
        float s = (v >= th) ? 1.f : ((v < -th) ? -1.f : 0.f);
        g_ws[sel][k][i] = __float2bfloat16(s);
    }
}

// x (NCHW fp32) -> NHWC bf16 hi/lo
__global__ void xprep_k(const float* __restrict__ x) {
    __shared__ float s[32][33];
    int img = blockIdx.z, c0 = blockIdx.y * 32, p0 = blockIdx.x * 32;
    int tx = threadIdx.x, ty = threadIdx.y;
#pragma unroll
    for (int r = 0; r < 4; r++)
        s[ty + r * 8][tx] = x[((size_t)img * 256 + c0 + ty + r * 8) * HWPIX + p0 + tx];
    __syncthreads();
#pragma unroll
    for (int r = 0; r < 4; r++) {
        float v = s[tx][ty + r * 8];
        __nv_bfloat16 h = __float2bfloat16(v);
        __nv_bfloat16 l = __float2bfloat16(v - __bfloat162float(h));
        size_t d = ((size_t)img * HWPIX + p0 + ty + r * 8) * 256 + c0 + tx;
        g_xhi[d] = h; g_xlo[d] = l;
    }
}

// ---------------- mma.sync conv ------------------------------------------------
// CTA: 128 co x 128 pix (2 out rows x 64 w), 8 warps of 64co x 32pix.
// K: 8 ci-chunks of 32. B smem: 260 in-rows (4 rows x 64 cols + 2 spill rows
// + pad), 32 ci x 2B = 64B data, row stride 80B, hi + lo. A: 128 x 64B, stride 80.
#define SB_LO 20800
#define SA    41600
#define SMSZ  51840

__global__ void __launch_bounds__(256, 2) conv_k(int src, int wsel, int dst) {
    extern __shared__ char smc[];
    const int tid = threadIdx.x;
    const int lane = tid & 31, warp = tid >> 5;
    const int g = lane >> 2, tg = lane & 3;
    const int wco = (warp >> 2) * 64;       // 0 / 64
    const int wpix = (warp & 3) * 32;       // 0..96
    const int h0 = blockIdx.x * 2, co0 = blockIdx.y * 128, img = blockIdx.z;

    const __nv_bfloat16* __restrict__ xhi = src ? g_ahi : g_xhi;
    const __nv_bfloat16* __restrict__ xlo = src ? g_alo : g_xlo;
    float* __restrict__ out = dst ? g_buf2 : g_buf1;

    float acc[4][4][4];
#pragma unroll
    for (int i = 0; i < 4; i++)
#pragma unroll
        for (int j = 0; j < 4; j++)
#pragma unroll
            for (int k = 0; k < 4; k++) acc[i][j][k] = 0.f;

    for (int ch = 0; ch < 8; ch++) {
        const int ci0 = ch * 32;
        __syncthreads();   // previous chunk's B readers done
        // ---- load B tile (hi+lo): row r=tid -> input (h0-1+r/64, r%64-1) ----
        {
            int r = tid;
            int ih = h0 - 1 + (r >> 6), iw = (r & 63) - 1;
            uint4 z = make_uint4(0, 0, 0, 0);
            uint4 h0v = z, h1v = z, h2v = z, h3v = z;
            uint4 l0v = z, l1v = z, l2v = z, l3v = z;
            if ((unsigned)ih < 56u && (unsigned)iw < 56u) {
                size_t s = ((size_t)img * HWPIX + ih * 56 + iw) * 256 + ci0;
                const uint4* ph = (const uint4*)(xhi + s);
                const uint4* pl = (const uint4*)(xlo + s);
                h0v = ph[0]; h1v = ph[1]; h2v = ph[2]; h3v = ph[3];
                l0v = pl[0]; l1v = pl[1]; l2v = pl[2]; l3v = pl[3];
            }
            char* bh = smc + r * 80;
            *(uint4*)(bh) = h0v; *(uint4*)(bh + 16) = h1v;
            *(uint4*)(bh + 32) = h2v; *(uint4*)(bh + 48) = h3v;
            char* bl = smc + SB_LO + r * 80;
            *(uint4*)(bl) = l0v; *(uint4*)(bl + 16) = l1v;
            *(uint4*)(bl + 32) = l2v; *(uint4*)(bl + 48) = l3v;
            if (tid < 8) {   // zero spill rows 256..259 (feed dead outputs only)
                int rr = 256 + (tid >> 1);
                int q = (tid & 1) * 32;
                char* zh = smc + rr * 80 + q;
                char* zl = smc + SB_LO + rr * 80 + q;
                *(uint4*)(zh) = z; *(uint4*)(zh + 16) = z;
                *(uint4*)(zl) = z; *(uint4*)(zl + 16) = z;
            }
        }
#pragma unroll 1
        for (int pos = 0; pos < 9; pos++) {
            if (pos > 0) __syncthreads();   // previous A readers done
            // ---- load A (sign weights) for this 3x3 position ----
            {
                int row = tid >> 1;
                int q = (tid & 1) * 2;
                const uint4* pw = (const uint4*)(g_ws[wsel][pos] +
                                                 (size_t)(co0 + row) * 256 + ci0);
                char* pa = smc + SA + row * 80 + q * 16;
                *(uint4*)(pa) = pw[q];
                *(uint4*)(pa + 16) = pw[q + 1];
            }
            __syncthreads();
            const int dlt = (pos / 3) * 64 + (pos % 3);
#pragma unroll
            for (int kk = 0; kk < 2; kk++) {
                const int kb = kk * 32 + tg * 4;
                uint32_t a[4][4];
#pragma unroll
                for (int mt = 0; mt < 4; mt++) {
                    const char* ab = smc + SA + (wco + mt * 16 + g) * 80 + kb;
                    a[mt][0] = *(const uint32_t*)(ab);
                    a[mt][1] = *(const uint32_t*)(ab + 8 * 80);
                    a[mt][2] = *(const uint32_t*)(ab + 16);
                    a[mt][3] = *(const uint32_t*)(ab + 8 * 80 + 16);
                }
#pragma unroll
                for (int nt = 0; nt < 4; nt++) {
                    const int prow = wpix + nt * 8 + g + dlt;
                    const char* bb = smc + prow * 80 + kb;
                    uint32_t bh[2], bl[2];
                    bh[0] = *(const uint32_t*)(bb);
                    bh[1] = *(const uint32_t*)(bb + 16);
                    bl[0] = *(const uint32_t*)(bb + SB_LO);
                    bl[1] = *(const uint32_t*)(bb + SB_LO + 16);
#pragma unroll
                    for (int mt = 0; mt < 4; mt++) mma16816(acc[mt][nt], a[mt], bh);
#pragma unroll
                    for (int mt = 0; mt < 4; mt++) mma16816(acc[mt][nt], a[mt], bl);
                }
            }
        }
    }

    // ---- epilogue: write NHWC fp32 ----
#pragma unroll
    for (int mt = 0; mt < 4; mt++) {
        int co = co0 + wco + mt * 16 + g;
#pragma unroll
        for (int nt = 0; nt < 4; nt++) {
            int n = wpix + nt * 8 + tg * 2;
            int ow = n & 63, oh = h0 + (n >> 6);
            if (ow < 56) {   // ow even: ow<56 implies ow+1<56
                size_t p = ((size_t)img * HWPIX + oh * 56 + ow) * 256;
                out[p + co] = acc[mt][nt][0];
                out[p + co + 8] = acc[mt][nt][2];
                out[p + 256 + co] = acc[mt][nt][1];
                out[p + 256 + co + 8] = acc[mt][nt][3];
            }
        }
    }
}

// ---------------- BN / epilogue kernels (NHWC) ---------------------------------
__global__ void bnstat_k(int which) {
    const float* __restrict__ v = which ? g_buf2 : g_buf1;
    int c = threadIdx.x;
    const float* p = v + (size_t)blockIdx.x * 784 * 256 + c;
    double s = 0.0, qq = 0.0;
#pragma unroll 4
    for (int i = 0; i < 784; i++) {
        double f = (double)p[(size_t)i * 256];
        s += f; qq += f * f;
    }
    atomicAdd(&g_bnsum[which][c], s);
    atomicAdd(&g_bnsq[which][c], qq);
}

__global__ void bnfin_k(const float* __restrict__ gamma,
                        const float* __restrict__ beta, int which) {
    int c = threadIdx.x;
    const double cnt = 64.0 * 3136.0;
    double mean = g_bnsum[which][c] / cnt;
    double var = g_bnsq[which][c] / cnt - mean * mean;
    unsigned long long wc = g_wcnt[which];
    double W = g_wsum[which] / (double)(wc ? wc : 1ull);
    if (W < 1e-30) W = 1e-30;
    double eps = 1e-5 / (W * W);   // fold dropped weight scale exactly into BN
    float sc = gamma[c] * (float)(1.0 / sqrt(var + eps));
    g_bnscale[which][c] = sc;
    g_bnshift[which][c] = beta[c] - (float)mean * sc;
}

// BN1 + ReLU + bf16 hi/lo split: g_buf1 -> g_ahi/g_alo
__global__ void actprep_k() {
    size_t i4 = (size_t)blockIdx.x * 256 + threadIdx.x;
    int c0 = ((int)i4 & 63) * 4;
    float4 v = ((const float4*)g_buf1)[i4];
    float4 sc = *(const float4*)&g_bnscale[0][c0];
    float4 sh = *(const float4*)&g_bnshift[0][c0];
    float a[4];
    a[0] = fmaxf(fmaf(v.x, sc.x, sh.x), 0.f);
    a[1] = fmaxf(fmaf(v.y, sc.y, sh.y), 0.f);
    a[2] = fmaxf(fmaf(v.z, sc.z, sh.z), 0.f);
    a[3] = fmaxf(fmaf(v.w, sc.w, sh.w), 0.f);
    __nv_bfloat162 h0, h1, l0, l1;
    h0.x = __float2bfloat16(a[0]); h0.y = __float2bfloat16(a[1]);
    h1.x = __float2bfloat16(a[2]); h1.y = __float2bfloat16(a[3]);
    l0.x = __float2bfloat16(a[0] - __bfloat162float(h0.x));
    l0.y = __float2bfloat16(a[1] - __bfloat162float(h0.y));
    l1.x = __float2bfloat16(a[2] - __bfloat162float(h1.x));
    l1.y = __float2bfloat16(a[3] - __bfloat162float(h1.y));
    ((__nv_bfloat162*)g_ahi)[i4 * 2] = h0;
    ((__nv_bfloat162*)g_ahi)[i4 * 2 + 1] = h1;
    ((__nv_bfloat162*)g_alo)[i4 * 2] = l0;
    ((__nv_bfloat162*)g_alo)[i4 * 2 + 1] = l1;
}

// BN2 + residual + ReLU, NHWC -> NCHW transpose into d_out
__global__ void final_k(const float* __restrict__ x, float* __restrict__ out) {
    __shared__ float s[32][33];
    int img = blockIdx.z, c0 = blockIdx.y * 32, p0 = blockIdx.x * 32;
    int tx = threadIdx.x, ty = threadIdx.y;
#pragma unroll
    for (int r = 0; r < 4; r++) {
        int pl = ty + r * 8;
        float v = g_buf2[((size_t)img * HWPIX + p0 + pl) * 256 + c0 + tx];
        s[pl][tx] = fmaf(v, g_bnscale[1][c0 + tx], g_bnshift[1][c0 + tx]);
    }
    __syncthreads();
#pragma unroll
    for (int r = 0; r < 4; r++) {
        int cl = ty + r * 8;
        size_t o = ((size_t)img * 256 + c0 + cl) * HWPIX + p0 + tx;
        out[o] = fmaxf(s[tx][cl] + x[o], 0.f);
    }
}

// -------------------------------------------------------------------------------
extern "C" void kernel_launch(void* const* d_in, const int* in_sizes, int n_in,
                              void* d_out, int out_size) {
    const float* x  = (const float*)d_in[0];
    const float* w1 = (const float*)d_in[1];
    const float* g1 = (const float*)d_in[2];
    const float* b1 = (const float*)d_in[3];
    const float* w2 = (const float*)d_in[4];
    const float* g2 = (const float*)d_in[5];
    const float* b2 = (const float*)d_in[6];
    float* out = (float*)d_out;

    static int attr_done = 0;
    if (!attr_done) {
        cudaFuncSetAttribute(conv_k, cudaFuncAttributeMaxDynamicSharedMemorySize,
                             SMSZ);
        attr_done = 1;
    }

    init_k<<<1, 256>>>();
    absmax_k<<<256, 256>>>(w1, 0);
    absmax_k<<<256, 256>>>(w2, 1);
    wsum_k<<<256, 256>>>(w1, 0);
    wsum_k<<<256, 256>>>(w2, 1);
    wsign_k<<<256, 256>>>(w1, 0);
    wsign_k<<<256, 256>>>(w2, 1);

    xprep_k<<<dim3(98, 8, 64), dim3(32, 8)>>>(x);

    dim3 cgrid(28, 2, 64);
    conv_k<<<cgrid, 256, SMSZ>>>(0, 0, 0);     // x(hi/lo) -> buf1
    bnstat_k<<<256, 256>>>(0);
    bnfin_k<<<1, 256>>>(g1, b1, 0);
    actprep_k<<<50176, 256>>>();               // buf1 -> ahi/alo

    conv_k<<<cgrid, 256, SMSZ>>>(1, 1, 1);     // act1 -> buf2
    bnstat_k<<<256, 256>>>(1);
    bnfin_k<<<1, 256>>>(g2, b2, 1);
    final_k<<<dim3(98, 8, 64), dim3(32, 8)>>>(x, out);
}